// round 11
// baseline (speedup 1.0000x reference)
#include <cuda_runtime.h>
#include <cuda_bf16.h>
#include <cstdint>

typedef unsigned long long u64;

// Problem constants
#define B 4
#define C 4
#define H 256
#define W 256
#define HW (H*W)          // 65536
#define FS 11
#define PAD 5

// Tile config
#define BW 32             // tile width (output pixels)
#define BH 8              // tile height
#define R  2              // pixels per thread along w
#define NSLOTS 128        // pixel-slots per block = (BW/R)*BH
#define NTHREADS 256      // 2 ki-groups x 128 slots
#define HALO_W (BW + FS - 1)   // 42
#define HALO_H (BH + FS - 1)   // 18
#define NHALO (HALO_H * HALO_W)  // 756
#define NHIT ((NHALO + NTHREADS - 1) / NTHREADS)   // 3
#define SST 43            // shared row stride in 16B units (bank-skewed)

__device__ __forceinline__ float ex2(float s) {
    float r;
    asm("ex2.approx.f32 %0, %1;" : "=f"(r) : "f"(s));
    return r;
}
__device__ __forceinline__ u64 packf2(float a, float b) {
    u64 d;
    asm("mov.b64 %0, {%1, %2};" : "=l"(d) : "f"(a), "f"(b));
    return d;
}
__device__ __forceinline__ float2 unpack2(u64 v) {
    float2 f;
    asm("mov.b64 {%0, %1}, %2;" : "=f"(f.x), "=f"(f.y) : "l"(v));
    return f;
}

// ---------------------------------------------------------------------------
// Single fused kernel, algebraically folded:
//   score_k = psi . x_k   with  psi = (Wp^T Wt) x_p  (pre-scaled by log2 e)
//   out     = M (sum_k att_k x_k) + x,  M = Ww Wg
// ki-split: group0 = window rows [0,5) + epilogue, group1 = rows [5,11).
// Register-minimal loop (2-deep window, scalar math) to keep 56 warps/SM.
// ---------------------------------------------------------------------------
__global__ __launch_bounds__(NTHREADS, 7) void fused_kernel(
    const float* __restrict__ x,
    const float* __restrict__ Wt,
    const float* __restrict__ Wp,
    const float* __restrict__ Wg,
    const float* __restrict__ Ww,
    float* __restrict__ out)
{
    __shared__ ulonglong2 xsh[HALO_H * SST];   // x halo: (c01, c23) f32 pairs
    __shared__ float wN[16];                   // N = Wp^T Wt, scaled by log2 e
    __shared__ float wM[16];                   // M = Ww Wg
    __shared__ float red[NSLOTS * 10];         // group1 partials

    int tid = threadIdx.x;

    int b  = blockIdx.z;
    int h0 = blockIdx.y * BH;
    int w0 = blockIdx.x * BW;
    const float* xb = x + b * (C * HW);

    // --- Small matrix products N, M (threads 0..31, one entry each) ---
    if (tid < 32) {
        int e = tid & 15;
        int i = e >> 2;       // row
        int j = e & 3;        // col
        if (tid < 16) {
            float s = Wp[i] * Wt[j];
            s = fmaf(Wp[4 + i],  Wt[4 + j],  s);
            s = fmaf(Wp[8 + i],  Wt[8 + j],  s);
            s = fmaf(Wp[12 + i], Wt[12 + j], s);
            wN[e] = s * 1.4426950408889634f;
        } else {
            float s = Ww[i*4 + 0] * Wg[j];
            s = fmaf(Ww[i*4 + 1], Wg[4 + j],  s);
            s = fmaf(Ww[i*4 + 2], Wg[8 + j],  s);
            s = fmaf(Ww[i*4 + 3], Wg[12 + j], s);
            wM[e] = s;
        }
    }

    // --- Halo: batch global loads (MLP), then shared stores ---
    float v0[NHIT], v1[NHIT], v2[NHIT], v3[NHIT];
    #pragma unroll
    for (int it = 0; it < NHIT; it++) {
        int idx = it * NTHREADS + tid;
        v0[it] = 0.f; v1[it] = 0.f; v2[it] = 0.f; v3[it] = 0.f;
        if (idx < NHALO) {
            int i  = idx / HALO_W;
            int j  = idx - i * HALO_W;
            int gh = h0 - PAD + i;
            int gw = w0 - PAD + j;
            if ((unsigned)gh < (unsigned)H && (unsigned)gw < (unsigned)W) {
                const float* xp = xb + gh * W + gw;
                v0[it] = xp[0];
                v1[it] = xp[HW];
                v2[it] = xp[2*HW];
                v3[it] = xp[3*HW];
            }
        }
    }
    #pragma unroll
    for (int it = 0; it < NHIT; it++) {
        int idx = it * NTHREADS + tid;
        if (idx < NHALO) {
            int i  = idx / HALO_W;
            int j  = idx - i * HALO_W;
            xsh[i * SST + j] = make_ulonglong2(packf2(v0[it], v1[it]),
                                               packf2(v2[it], v3[it]));
        }
    }
    __syncthreads();

    // --- Slot mapping (identical bank-verified map per 128-slot group) ---
    int grp  = tid >> 7;          // 0 or 1
    int slot = tid & 127;
    int tx = (slot >> 1) & 15;
    int ty = ((slot >> 5) << 1) | (slot & 1);

    // Own pixels re-read from the shared halo (saves loop-resident registers)
    int ownoff = (ty + PAD) * SST + (PAD + tx * R);
    ulonglong2 X0 = xsh[ownoff];
    ulonglong2 X1 = xsh[ownoff + 1];
    float2 x0a = unpack2(X0.x), x0b = unpack2(X0.y);
    float2 x1a = unpack2(X1.x), x1b = unpack2(X1.y);

    // psi = N x_p per own pixel (scalar)
    float p00 = fmaf(wN[0],  x0a.x, fmaf(wN[1],  x0a.y, fmaf(wN[2],  x0b.x, wN[3]  * x0b.y)));
    float p01 = fmaf(wN[4],  x0a.x, fmaf(wN[5],  x0a.y, fmaf(wN[6],  x0b.x, wN[7]  * x0b.y)));
    float p02 = fmaf(wN[8],  x0a.x, fmaf(wN[9],  x0a.y, fmaf(wN[10], x0b.x, wN[11] * x0b.y)));
    float p03 = fmaf(wN[12], x0a.x, fmaf(wN[13], x0a.y, fmaf(wN[14], x0b.x, wN[15] * x0b.y)));
    float p10 = fmaf(wN[0],  x1a.x, fmaf(wN[1],  x1a.y, fmaf(wN[2],  x1b.x, wN[3]  * x1b.y)));
    float p11 = fmaf(wN[4],  x1a.x, fmaf(wN[5],  x1a.y, fmaf(wN[6],  x1b.x, wN[7]  * x1b.y)));
    float p12 = fmaf(wN[8],  x1a.x, fmaf(wN[9],  x1a.y, fmaf(wN[10], x1b.x, wN[11] * x1b.y)));
    float p13 = fmaf(wN[12], x1a.x, fmaf(wN[13], x1a.y, fmaf(wN[14], x1b.x, wN[15] * x1b.y)));

    float acc00 = 0.f, acc01 = 0.f, acc02 = 0.f, acc03 = 0.f, sum0 = 0.f;
    float acc10 = 0.f, acc11 = 0.f, acc12 = 0.f, acc13 = 0.f, sum1 = 0.f;

    // ki range: group0 rows [0,5), group1 rows [5,11)
    int ki0 = grp ? 5 : 0;
    int nki = grp ? 6 : 5;

    const ulonglong2* row = &xsh[ty * SST + tx * R + ki0 * SST];

    #pragma unroll 1
    for (int k = 0; k < nki; k++) {
        ulonglong2 cur = row[0];
        #pragma unroll
        for (int kj = 0; kj < FS; kj++) {
            ulonglong2 nxt = row[kj + 1];   // kj+1 <= 11; max col 30+11=41 < 42
            float2 ca = unpack2(cur.x), cb = unpack2(cur.y);
            float2 na = unpack2(nxt.x), nb = unpack2(nxt.y);
            float s0 = fmaf(p00, ca.x, fmaf(p01, ca.y, fmaf(p02, cb.x, p03 * cb.y)));
            float s1 = fmaf(p10, na.x, fmaf(p11, na.y, fmaf(p12, nb.x, p13 * nb.y)));
            float e0 = ex2(s0);
            float e1 = ex2(s1);
            sum0 += e0;
            sum1 += e1;
            acc00 = fmaf(e0, ca.x, acc00);
            acc01 = fmaf(e0, ca.y, acc01);
            acc02 = fmaf(e0, cb.x, acc02);
            acc03 = fmaf(e0, cb.y, acc03);
            acc10 = fmaf(e1, na.x, acc10);
            acc11 = fmaf(e1, na.y, acc11);
            acc12 = fmaf(e1, nb.x, acc12);
            acc13 = fmaf(e1, nb.y, acc13);
            cur = nxt;
        }
        row += SST;
    }

    // --- Combine: group1 publishes partials; group0 adds + epilogue ---
    if (grp == 1) {
        float* rp = &red[slot * 10];
        rp[0] = acc00; rp[1] = acc01; rp[2] = acc02; rp[3] = acc03; rp[4] = sum0;
        rp[5] = acc10; rp[6] = acc11; rp[7] = acc12; rp[8] = acc13; rp[9] = sum1;
    }
    __syncthreads();
    if (grp == 0) {
        const float* rp = &red[slot * 10];
        acc00 += rp[0]; acc01 += rp[1]; acc02 += rp[2]; acc03 += rp[3]; sum0 += rp[4];
        acc10 += rp[5]; acc11 += rp[6]; acc12 += rp[7]; acc13 += rp[8]; sum1 += rp[9];

        float inv0 = __frcp_rn(sum0);
        float inv1 = __frcp_rn(sum1);
        float a0[2] = { acc00 * inv0, acc10 * inv1 };
        float a1[2] = { acc01 * inv0, acc11 * inv1 };
        float a2[2] = { acc02 * inv0, acc12 * inv1 };
        float a3[2] = { acc03 * inv0, acc13 * inv1 };
        float xr[4][2] = { { x0a.x, x1a.x }, { x0a.y, x1a.y },
                           { x0b.x, x1b.x }, { x0b.y, x1b.y } };

        int pixbase = (h0 + ty) * W + w0 + tx * R;
        float* ob = out + b * (C * HW);
        #pragma unroll
        for (int c = 0; c < C; c++) {
            float2 res;
            res.x = fmaf(wM[c*4+0], a0[0], fmaf(wM[c*4+1], a1[0], fmaf(wM[c*4+2], a2[0], wM[c*4+3] * a3[0]))) + xr[c][0];
            res.y = fmaf(wM[c*4+0], a0[1], fmaf(wM[c*4+1], a1[1], fmaf(wM[c*4+2], a2[1], wM[c*4+3] * a3[1]))) + xr[c][1];
            *(float2*)(ob + c * HW + pixbase) = res;
        }
    }
}

// ---------------------------------------------------------------------------
extern "C" void kernel_launch(void* const* d_in, const int* in_sizes, int n_in,
                              void* d_out, int out_size)
{
    const float* x  = (const float*)d_in[0];
    const float* Wt = (const float*)d_in[1];
    const float* Wp = (const float*)d_in[2];
    const float* Wg = (const float*)d_in[3];
    const float* Ww = (const float*)d_in[4];
    float* out = (float*)d_out;

    dim3 grid(W / BW, H / BH, B);
    fused_kernel<<<grid, NTHREADS>>>(x, Wt, Wp, Wg, Ww, out);
}

// round 12
// speedup vs baseline: 1.0875x; 1.0875x over previous
#include <cuda_runtime.h>
#include <cuda_bf16.h>
#include <cstdint>

typedef unsigned long long u64;

// Problem constants
#define B 4
#define C 4
#define H 256
#define W 256
#define HW (H*W)          // 65536
#define FS 11
#define PAD 5

// Tile config
#define BW 32             // tile width (output pixels)
#define BH 8              // tile height
#define R  2              // pixels per thread along w
#define NTHREADS 128      // (BW/R) * BH = 16 * 8
#define HALO_W (BW + FS - 1)   // 42
#define HALO_H (BH + FS - 1)   // 18
#define NHALO (HALO_H * HALO_W)  // 756
#define NHIT ((NHALO + NTHREADS - 1) / NTHREADS)   // 6
#define SST 43            // shared row stride in 16B units (bank-skewed)

__device__ __forceinline__ float ex2(float s) {
    float r;
    asm("ex2.approx.f32 %0, %1;" : "=f"(r) : "f"(s));
    return r;
}
__device__ __forceinline__ u64 fma2(u64 a, u64 b, u64 c) {
    u64 d;
    asm("fma.rn.f32x2 %0, %1, %2, %3;" : "=l"(d) : "l"(a), "l"(b), "l"(c));
    return d;
}
__device__ __forceinline__ u64 mul2(u64 a, u64 b) {
    u64 d;
    asm("mul.rn.f32x2 %0, %1, %2;" : "=l"(d) : "l"(a), "l"(b));
    return d;
}
__device__ __forceinline__ u64 packf2(float a, float b) {
    u64 d;
    asm("mov.b64 %0, {%1, %2};" : "=l"(d) : "f"(a), "f"(b));
    return d;
}
__device__ __forceinline__ float2 unpack2(u64 v) {
    float2 f;
    asm("mov.b64 {%0, %1}, %2;" : "=f"(f.x), "=f"(f.y) : "l"(v));
    return f;
}

// ---------------------------------------------------------------------------
// Single fused kernel, algebraically folded:
//   score_k = psi . x_k   with  psi = (Wp^T Wt) x_p  (pre-scaled by log2 e)
//   out     = M (sum_k att_k x_k) + x,  M = Ww Wg
// Score: packed f32x2 (naturally pair-aligned). Accumulate: scalar FFMA.
// Fully-unrolled 11x11 main loop (software-pipelined by ptxas).
// ---------------------------------------------------------------------------
__global__ __launch_bounds__(NTHREADS, 7) void fused_kernel(
    const float* __restrict__ x,
    const float* __restrict__ Wt,
    const float* __restrict__ Wp,
    const float* __restrict__ Wg,
    const float* __restrict__ Ww,
    float* __restrict__ out)
{
    __shared__ ulonglong2 xsh[HALO_H * SST];   // x halo: (c01, c23) f32 pairs
    __shared__ float wN[16];                   // N = Wp^T Wt, scaled by log2 e
    __shared__ float wM[16];                   // M = Ww Wg

    int tid = threadIdx.x;

    int b  = blockIdx.z;
    int h0 = blockIdx.y * BH;
    int w0 = blockIdx.x * BW;
    const float* xb = x + b * (C * HW);

    // --- Small matrix products N, M (threads 0..31, one entry each) ---
    if (tid < 32) {
        int e = tid & 15;
        int i = e >> 2;       // row
        int j = e & 3;        // col
        if (tid < 16) {
            float s = Wp[i] * Wt[j];
            s = fmaf(Wp[4 + i],  Wt[4 + j],  s);
            s = fmaf(Wp[8 + i],  Wt[8 + j],  s);
            s = fmaf(Wp[12 + i], Wt[12 + j], s);
            wN[e] = s * 1.4426950408889634f;
        } else {
            float s = Ww[i*4 + 0] * Wg[j];
            s = fmaf(Ww[i*4 + 1], Wg[4 + j],  s);
            s = fmaf(Ww[i*4 + 2], Wg[8 + j],  s);
            s = fmaf(Ww[i*4 + 3], Wg[12 + j], s);
            wM[e] = s;
        }
    }

    // --- Halo: batch ALL global loads first (MLP), then shared stores ---
    float v0[NHIT], v1[NHIT], v2[NHIT], v3[NHIT];
    #pragma unroll
    for (int it = 0; it < NHIT; it++) {
        int idx = it * NTHREADS + tid;
        v0[it] = 0.f; v1[it] = 0.f; v2[it] = 0.f; v3[it] = 0.f;
        if (idx < NHALO) {
            int i  = idx / HALO_W;
            int j  = idx - i * HALO_W;
            int gh = h0 - PAD + i;
            int gw = w0 - PAD + j;
            if ((unsigned)gh < (unsigned)H && (unsigned)gw < (unsigned)W) {
                const float* xp = xb + gh * W + gw;
                v0[it] = xp[0];
                v1[it] = xp[HW];
                v2[it] = xp[2*HW];
                v3[it] = xp[3*HW];
            }
        }
    }
    #pragma unroll
    for (int it = 0; it < NHIT; it++) {
        int idx = it * NTHREADS + tid;
        if (idx < NHALO) {
            int i  = idx / HALO_W;
            int j  = idx - i * HALO_W;
            xsh[i * SST + j] = make_ulonglong2(packf2(v0[it], v1[it]),
                                               packf2(v2[it], v3[it]));
        }
    }

    // --- Own-pixel x loads (for psi and residual) ---
    // Lane mapping: ty = lane&1 (+2 per warp), tx = (lane>>1)&15.
    // Conflict-free 8-lane LDS.128 phases given SST=43.
    int tx = (tid >> 1) & 15;
    int ty = ((tid >> 5) << 1) | (tid & 1);
    int oh = h0 + ty;
    int ow = w0 + tx * R;
    int pixbase = oh * W + ow;

    float xs[4][R];
    #pragma unroll
    for (int c = 0; c < 4; c++) {
        float2 v = *(const float2*)(xb + c * HW + pixbase);
        xs[c][0] = v.x; xs[c][1] = v.y;
    }
    __syncthreads();

    // --- psi = N x_p (per own pixel), packed as f32x2 pairs ---
    u64 psiA[R], psiB[R];
    float acc0[R], acc1[R], acc2[R], acc3[R], sum[R];
    #pragma unroll
    for (int r = 0; r < R; r++) {
        float p0 = fmaf(wN[0],  xs[0][r], fmaf(wN[1],  xs[1][r], fmaf(wN[2],  xs[2][r], wN[3]  * xs[3][r])));
        float p1 = fmaf(wN[4],  xs[0][r], fmaf(wN[5],  xs[1][r], fmaf(wN[6],  xs[2][r], wN[7]  * xs[3][r])));
        float p2 = fmaf(wN[8],  xs[0][r], fmaf(wN[9],  xs[1][r], fmaf(wN[10], xs[2][r], wN[11] * xs[3][r])));
        float p3 = fmaf(wN[12], xs[0][r], fmaf(wN[13], xs[1][r], fmaf(wN[14], xs[2][r], wN[15] * xs[3][r])));
        psiA[r] = packf2(p0, p1);
        psiB[r] = packf2(p2, p3);
        acc0[r] = 0.f; acc1[r] = 0.f; acc2[r] = 0.f; acc3[r] = 0.f;
        sum[r] = 0.f;
    }

    int base = ty * SST + tx * R;

    // --- Main loop: FULLY UNROLLED 11 rows x 11 cols ---
    #pragma unroll
    for (int ki = 0; ki < FS; ki++) {
        const ulonglong2* row = &xsh[base + ki * SST];
        ulonglong2 xw[4];
        xw[0] = row[0]; xw[1] = row[1]; xw[2] = row[2];
        #pragma unroll
        for (int kj = 0; kj < FS; kj++) {
            if (kj < 9) xw[(kj + 3) & 3] = row[kj + 3];   // compile-time guard
            #pragma unroll
            for (int r = 0; r < R; r++) {
                ulonglong2 X = xw[(kj + r) & 3];
                u64 t = mul2(psiA[r], X.x);
                t = fma2(psiB[r], X.y, t);
                float2 f = unpack2(t);
                float e = ex2(f.x + f.y);       // psi pre-scaled by log2 e
                sum[r] += e;
                float2 xa = unpack2(X.x);       // pure register renaming
                float2 xc = unpack2(X.y);
                acc0[r] = fmaf(e, xa.x, acc0[r]);
                acc1[r] = fmaf(e, xa.y, acc1[r]);
                acc2[r] = fmaf(e, xc.x, acc2[r]);
                acc3[r] = fmaf(e, xc.y, acc3[r]);
            }
        }
    }

    // --- Epilogue: normalize, apply M, residual; float2 stores ---
    float a0[R], a1[R], a2[R], a3[R];
    #pragma unroll
    for (int r = 0; r < R; r++) {
        float inv = __frcp_rn(sum[r]);
        a0[r] = acc0[r] * inv;
        a1[r] = acc1[r] * inv;
        a2[r] = acc2[r] * inv;
        a3[r] = acc3[r] * inv;
    }
    float* ob = out + b * (C * HW);
    #pragma unroll
    for (int c = 0; c < C; c++) {
        float2 res;
        res.x = fmaf(wM[c*4+0], a0[0], fmaf(wM[c*4+1], a1[0], fmaf(wM[c*4+2], a2[0], wM[c*4+3] * a3[0]))) + xs[c][0];
        res.y = fmaf(wM[c*4+0], a0[1], fmaf(wM[c*4+1], a1[1], fmaf(wM[c*4+2], a2[1], wM[c*4+3] * a3[1]))) + xs[c][1];
        *(float2*)(ob + c * HW + pixbase) = res;
    }
}

// ---------------------------------------------------------------------------
extern "C" void kernel_launch(void* const* d_in, const int* in_sizes, int n_in,
                              void* d_out, int out_size)
{
    const float* x  = (const float*)d_in[0];
    const float* Wt = (const float*)d_in[1];
    const float* Wp = (const float*)d_in[2];
    const float* Wg = (const float*)d_in[3];
    const float* Ww = (const float*)d_in[4];
    float* out = (float*)d_out;

    dim3 grid(W / BW, H / BH, B);
    fused_kernel<<<grid, NTHREADS>>>(x, Wt, Wp, Wg, Ww, out);
}